// round 3
// baseline (speedup 1.0000x reference)
#include <cuda_runtime.h>
#include <cuda_bf16.h>

// Problem constants (fixed shapes)
#define NN      50000
#define CC      32
#define HH      32
#define EE      1600000
#define NH      1600000      // N*H floats in result vector
#define NH4     400000       // NH / 4
#define FC      64
#define NCLS    2
#define BN_EPS  1e-5f

#define GEMV_BLOCKS 592
#define GEMV_THREADS 256
#define GEMV_CHUNKS ((NH4 + GEMV_THREADS - 1) / GEMV_THREADS)   // 1563

// Scratch (device globals; no allocation allowed)
__device__ __align__(16) float g_y [NN * HH];   // bn(x) @ Wsum
__device__ __align__(16) float g_y0[NN * HH];   // bn(x) @ W0
__device__ __align__(16) float g_res[NN * HH];  // scattered pre-relu result
__device__ float g_hacc[FC];
__device__ unsigned int g_sem;

// ---------------------------------------------------------------------------
// Kernel 1: BN (eval) + project through Wsum / W0, zero accumulators.
// One warp per node, lane = h (= c for the load).
// ---------------------------------------------------------------------------
__global__ __launch_bounds__(256)
void proj_kernel(const float* __restrict__ x,
                 const float* __restrict__ gamma,
                 const float* __restrict__ beta,
                 const float* __restrict__ mean,
                 const float* __restrict__ var,
                 const float* __restrict__ W) {   // [3,32,32]
    __shared__ float sW0[CC * HH];
    __shared__ float sWs[CC * HH];
    for (int i = threadIdx.x; i < CC * HH; i += blockDim.x) {
        sW0[i] = W[i];
        sWs[i] = W[CC * HH + i] + W[2 * CC * HH + i];
    }
    __syncthreads();

    int i = blockIdx.x * blockDim.x + threadIdx.x;   // covers exactly N*32
    int lane = i & 31;

    float xv = x[i];
    float s = rsqrtf(var[lane] + BN_EPS) * gamma[lane];
    float xb = (xv - mean[lane]) * s + beta[lane];

    float y = 0.0f, y0 = 0.0f;
#pragma unroll
    for (int c = 0; c < CC; c++) {
        float xc = __shfl_sync(0xffffffffu, xb, c);
        y  = fmaf(xc, sWs[c * HH + lane], y);
        y0 = fmaf(xc, sW0[c * HH + lane], y0);
    }
    g_y[i]  = y;
    g_y0[i] = y0;
    g_res[i] = 0.0f;

    if (blockIdx.x == 0) {
        if (threadIdx.x < FC) g_hacc[threadIdx.x] = 0.0f;
        if (threadIdx.x == 0) g_sem = 0u;
    }
}

// ---------------------------------------------------------------------------
// Kernel 2: edge scatter with vector global reductions into g_res
// ---------------------------------------------------------------------------
__device__ __forceinline__ void red_add_v4(float* p, float a, float b, float c, float d) {
    asm volatile("red.global.add.v4.f32 [%0], {%1, %2, %3, %4};"
                 :: "l"(p), "f"(a), "f"(b), "f"(c), "f"(d) : "memory");
}

__global__ __launch_bounds__(256)
void scatter_kernel(const int* __restrict__ edge_index,
                    const float* __restrict__ edge_weight) {
    int e = blockIdx.x * blockDim.x + threadIdx.x;
    if (e >= EE) return;
    int s = edge_index[e];
    int d = edge_index[EE + e];
    float w = edge_weight[e];

    const float4* yr = reinterpret_cast<const float4*>(g_y + (size_t)s * HH);
    float* rr = g_res + (size_t)d * HH;

    float4 v[8];
#pragma unroll
    for (int k = 0; k < 8; k++) v[k] = yr[k];
#pragma unroll
    for (int k = 0; k < 8; k++)
        red_add_v4(rr + 4 * k, w * v[k].x, w * v[k].y, w * v[k].z, w * v[k].w);

    if (s == d) {   // self-loop: T_0 identity term with weight 1.0
        const float4* y0r = reinterpret_cast<const float4*>(g_y0 + (size_t)s * HH);
#pragma unroll
        for (int k = 0; k < 8; k++) {
            float4 u = y0r[k];
            red_add_v4(rr + 4 * k, u.x, u.y, u.z, u.w);
        }
    }
}

// ---------------------------------------------------------------------------
// Kernel 3: streaming GEMV  h[f] = sum_i relu(res[i]) * fc1_w[f, i]
// + fused head (last block): out = relu(h + fc1_b) @ fc2_w^T + fc2_b
// ---------------------------------------------------------------------------
__global__ __launch_bounds__(GEMV_THREADS, 2)
void gemv_head_kernel(const float* __restrict__ fc1_w,
                      const float* __restrict__ fc1_b,
                      const float* __restrict__ fc2_w,
                      const float* __restrict__ fc2_b,
                      float* __restrict__ out) {
    const float4* R4 = reinterpret_cast<const float4*>(g_res);
    const float4* W4 = reinterpret_cast<const float4*>(fc1_w);

    float acc[FC];
#pragma unroll
    for (int f = 0; f < FC; f++) acc[f] = 0.0f;

    for (int chunk = blockIdx.x; chunk < GEMV_CHUNKS; chunk += gridDim.x) {
        int i4 = chunk * GEMV_THREADS + threadIdx.x;
        if (i4 < NH4) {
            float4 v = R4[i4];
            v.x = fmaxf(v.x, 0.0f); v.y = fmaxf(v.y, 0.0f);
            v.z = fmaxf(v.z, 0.0f); v.w = fmaxf(v.w, 0.0f);
#pragma unroll
            for (int f = 0; f < FC; f++) {
                float4 wv = __ldcs(W4 + (size_t)f * NH4 + i4);
                acc[f] = fmaf(v.x, wv.x, acc[f]);
                acc[f] = fmaf(v.y, wv.y, acc[f]);
                acc[f] = fmaf(v.z, wv.z, acc[f]);
                acc[f] = fmaf(v.w, wv.w, acc[f]);
            }
        }
    }

    // block reduction of the 64 accumulators
    __shared__ float sAcc[FC];
    for (int i = threadIdx.x; i < FC; i += blockDim.x) sAcc[i] = 0.0f;
    __syncthreads();

    const int lane = threadIdx.x & 31;
#pragma unroll
    for (int f = 0; f < FC; f++) {
        float v = acc[f];
        v += __shfl_xor_sync(0xffffffffu, v, 16);
        v += __shfl_xor_sync(0xffffffffu, v, 8);
        v += __shfl_xor_sync(0xffffffffu, v, 4);
        v += __shfl_xor_sync(0xffffffffu, v, 2);
        v += __shfl_xor_sync(0xffffffffu, v, 1);
        if (lane == 0) atomicAdd(&sAcc[f], v);
    }
    __syncthreads();
    if (threadIdx.x < FC) atomicAdd(&g_hacc[threadIdx.x], sAcc[threadIdx.x]);
    __syncthreads();

    // last-block head
    __shared__ bool isLast;
    if (threadIdx.x == 0) {
        __threadfence();
        unsigned int t = atomicAdd(&g_sem, 1u);
        isLast = (t == (unsigned int)(gridDim.x - 1));
    }
    __syncthreads();
    if (isLast) {
        __threadfence();
        __shared__ float hv[FC];
        volatile float* vh = g_hacc;
        if (threadIdx.x < FC)
            hv[threadIdx.x] = fmaxf(vh[threadIdx.x] + fc1_b[threadIdx.x], 0.0f);
        __syncthreads();
        if (threadIdx.x < NCLS) {
            float s = fc2_b[threadIdx.x];
#pragma unroll
            for (int f = 0; f < FC; f++)
                s = fmaf(hv[f], fc2_w[threadIdx.x * FC + f], s);
            out[threadIdx.x] = s;
        }
    }
}

// ---------------------------------------------------------------------------
// launch
// ---------------------------------------------------------------------------
extern "C" void kernel_launch(void* const* d_in, const int* in_sizes, int n_in,
                              void* d_out, int out_size) {
    const float* x        = (const float*)d_in[0];
    const float* ew       = (const float*)d_in[1];
    const float* W        = (const float*)d_in[2];
    const float* bn_gamma = (const float*)d_in[3];
    const float* bn_beta  = (const float*)d_in[4];
    const float* bn_mean  = (const float*)d_in[5];
    const float* bn_var   = (const float*)d_in[6];
    const float* fc1_w    = (const float*)d_in[7];
    const float* fc1_b    = (const float*)d_in[8];
    const float* fc2_w    = (const float*)d_in[9];
    const float* fc2_b    = (const float*)d_in[10];
    const int*   ei       = (const int*)d_in[11];
    float* out            = (float*)d_out;

    proj_kernel<<<(NN * HH) / 256, 256>>>(x, bn_gamma, bn_beta, bn_mean, bn_var, W);
    scatter_kernel<<<(EE + 255) / 256, 256>>>(ei, ew);
    gemv_head_kernel<<<GEMV_BLOCKS, GEMV_THREADS>>>(fc1_w, fc1_b, fc2_w, fc2_b, out);
}

// round 4
// speedup vs baseline: 1.0255x; 1.0255x over previous
#include <cuda_runtime.h>

// Problem constants (fixed shapes)
#define NN      50000
#define CC      32
#define HH      32
#define EE      1600000
#define NH      1600000
#define NH4     400000
#define FC      64
#define NCLS    2
#define BN_EPS  1e-5f

#define TILES   196          // ceil(NN / 256)
#define GEMV_BLOCKS 592
#define GEMV_THREADS 256
#define GEMV_CHUNKS ((NH4 + GEMV_THREADS - 1) / GEMV_THREADS)

// Scratch (device globals; no allocation allowed)
__device__ __align__(16) float g_xbn[NN * CC];
__device__ __align__(16) float g_y[NN * HH];
__device__ __align__(16) float g_res[NN * HH];
__device__ __align__(16) uint2 g_edges[EE];       // bucketed (src, w)
__device__ unsigned g_cnt[TILES * 256];           // padded dst histogram
__device__ unsigned g_rowstart[NN + 1];
__device__ unsigned g_cursor[NN];
__device__ unsigned g_bsum[256];                  // tile sums -> tile offsets
__device__ float g_hacc[FC];
__device__ unsigned g_sem;

// ---------------------------------------------------------------------------
// Kernel 1: BN (eval), y = xb @ (W1+W2), keep xbn, zero bookkeeping
// ---------------------------------------------------------------------------
__global__ __launch_bounds__(256)
void proj_kernel(const float* __restrict__ x,
                 const float* __restrict__ gamma,
                 const float* __restrict__ beta,
                 const float* __restrict__ mean,
                 const float* __restrict__ var,
                 const float* __restrict__ W) {
    __shared__ float sWs[CC * HH];
    for (int i = threadIdx.x; i < CC * HH; i += blockDim.x)
        sWs[i] = W[CC * HH + i] + W[2 * CC * HH + i];
    __syncthreads();

    int i = blockIdx.x * blockDim.x + threadIdx.x;   // exactly NN*CC threads
    int lane = i & 31;

    float xv = x[i];
    float s = rsqrtf(var[lane] + BN_EPS) * gamma[lane];
    float xb = (xv - mean[lane]) * s + beta[lane];
    g_xbn[i] = xb;

    float y = 0.0f;
#pragma unroll
    for (int c = 0; c < CC; c++)
        y = fmaf(__shfl_sync(0xffffffffu, xb, c), sWs[c * HH + lane], y);
    g_y[i] = y;

    if (i < TILES * 256) g_cnt[i] = 0u;
    if (i < FC) g_hacc[i] = 0.0f;
    if (i == 0) g_sem = 0u;
}

// ---------------------------------------------------------------------------
// Kernel 2: dst histogram
// ---------------------------------------------------------------------------
__global__ __launch_bounds__(256)
void hist_kernel(const int* __restrict__ edge_index) {
    int e = blockIdx.x * blockDim.x + threadIdx.x;
    if (e < EE) atomicAdd(&g_cnt[edge_index[EE + e]], 1u);
}

// ---------------------------------------------------------------------------
// Kernel 3a/3b/3c: 3-phase exclusive scan of the histogram
// ---------------------------------------------------------------------------
__global__ void scanA_kernel() {                 // per-tile sums
    __shared__ unsigned sh[256];
    unsigned v = g_cnt[blockIdx.x * 256 + threadIdx.x];
    sh[threadIdx.x] = v;
    __syncthreads();
    for (int o = 128; o > 0; o >>= 1) {
        if (threadIdx.x < o) sh[threadIdx.x] += sh[threadIdx.x + o];
        __syncthreads();
    }
    if (threadIdx.x == 0) g_bsum[blockIdx.x] = sh[0];
}

__global__ void scanB_kernel() {                 // exclusive scan of tile sums
    __shared__ unsigned a[256], b[256];
    unsigned v = (threadIdx.x < TILES) ? g_bsum[threadIdx.x] : 0u;
    a[threadIdx.x] = v;
    __syncthreads();
    unsigned* src = a; unsigned* dst = b;
    for (int o = 1; o < 256; o <<= 1) {
        unsigned t = src[threadIdx.x];
        if (threadIdx.x >= o) t += src[threadIdx.x - o];
        dst[threadIdx.x] = t;
        __syncthreads();
        unsigned* tmp = src; src = dst; dst = tmp;
    }
    g_bsum[threadIdx.x] = src[threadIdx.x] - v;   // exclusive
    if (threadIdx.x == 0) g_rowstart[NN] = EE;
}

__global__ void scanC_kernel() {                 // per-tile exclusive scan + offset
    __shared__ unsigned a[256], b[256];
    int idx = blockIdx.x * 256 + threadIdx.x;
    unsigned v = g_cnt[idx];
    a[threadIdx.x] = v;
    __syncthreads();
    unsigned* src = a; unsigned* dst = b;
    for (int o = 1; o < 256; o <<= 1) {
        unsigned t = src[threadIdx.x];
        if (threadIdx.x >= o) t += src[threadIdx.x - o];
        dst[threadIdx.x] = t;
        __syncthreads();
        unsigned* tmp = src; src = dst; dst = tmp;
    }
    unsigned excl = src[threadIdx.x] - v + g_bsum[blockIdx.x];
    if (idx < NN) {
        g_rowstart[idx] = excl;
        g_cursor[idx] = excl;
    }
}

// ---------------------------------------------------------------------------
// Kernel 4: reorder edges into dst buckets
// ---------------------------------------------------------------------------
__global__ __launch_bounds__(256)
void reorder_kernel(const int* __restrict__ edge_index,
                    const float* __restrict__ edge_weight) {
    int e = blockIdx.x * blockDim.x + threadIdx.x;
    if (e >= EE) return;
    int s = edge_index[e];
    int d = edge_index[EE + e];
    float w = edge_weight[e];
    unsigned pos = atomicAdd(&g_cursor[d], 1u);
    g_edges[pos] = make_uint2((unsigned)s, __float_as_uint(w));
}

// ---------------------------------------------------------------------------
// Kernel 5: CSR gather — warp per node, register accumulation, no atomics
// ---------------------------------------------------------------------------
__global__ __launch_bounds__(256)
void gather_kernel(const float* __restrict__ W) {   // W[0] block for self-loops
    int warp = (blockIdx.x * blockDim.x + threadIdx.x) >> 5;
    int lane = threadIdx.x & 31;
    if (warp >= NN) return;
    int n = warp;

    unsigned beg = g_rowstart[n];
    unsigned end = g_rowstart[n + 1];

    float acc = 0.0f;
    for (unsigned j = beg; j < end; j += 32) {
        int m = min(32u, end - j);
        uint2 ed = (j + (unsigned)lane < end) ? g_edges[j + lane]
                                              : make_uint2(0u, 0u);
        for (int i = 0; i < m; i++) {
            int   src = (int)__shfl_sync(0xffffffffu, ed.x, i);
            float w   = __uint_as_float(__shfl_sync(0xffffffffu, ed.y, i));
            acc = fmaf(w, g_y[(size_t)src * HH + lane], acc);
            if (src == n) {   // self-loop: k=0 identity term, weight 1.0
                float xc = g_xbn[(size_t)n * CC + lane];
#pragma unroll
                for (int c = 0; c < CC; c++)
                    acc = fmaf(__shfl_sync(0xffffffffu, xc, c),
                               __ldg(&W[c * HH + lane]), acc);
            }
        }
    }
    g_res[(size_t)n * HH + lane] = acc;
}

// ---------------------------------------------------------------------------
// Kernel 6: streaming GEMV h[f] = sum relu(res)*fc1_w[f] + fused head
// ---------------------------------------------------------------------------
__global__ __launch_bounds__(GEMV_THREADS, 2)
void gemv_head_kernel(const float* __restrict__ fc1_w,
                      const float* __restrict__ fc1_b,
                      const float* __restrict__ fc2_w,
                      const float* __restrict__ fc2_b,
                      float* __restrict__ out) {
    const float4* R4 = reinterpret_cast<const float4*>(g_res);
    const float4* W4 = reinterpret_cast<const float4*>(fc1_w);

    float acc[FC];
#pragma unroll
    for (int f = 0; f < FC; f++) acc[f] = 0.0f;

    for (int chunk = blockIdx.x; chunk < GEMV_CHUNKS; chunk += gridDim.x) {
        int i4 = chunk * GEMV_THREADS + threadIdx.x;
        if (i4 < NH4) {
            float4 v = R4[i4];
            v.x = fmaxf(v.x, 0.0f); v.y = fmaxf(v.y, 0.0f);
            v.z = fmaxf(v.z, 0.0f); v.w = fmaxf(v.w, 0.0f);
#pragma unroll
            for (int f = 0; f < FC; f++) {
                float4 wv = __ldcs(W4 + (size_t)f * NH4 + i4);
                acc[f] = fmaf(v.x, wv.x, acc[f]);
                acc[f] = fmaf(v.y, wv.y, acc[f]);
                acc[f] = fmaf(v.z, wv.z, acc[f]);
                acc[f] = fmaf(v.w, wv.w, acc[f]);
            }
        }
    }

    __shared__ float sAcc[FC];
    for (int i = threadIdx.x; i < FC; i += blockDim.x) sAcc[i] = 0.0f;
    __syncthreads();

    const int lane = threadIdx.x & 31;
#pragma unroll
    for (int f = 0; f < FC; f++) {
        float v = acc[f];
        v += __shfl_xor_sync(0xffffffffu, v, 16);
        v += __shfl_xor_sync(0xffffffffu, v, 8);
        v += __shfl_xor_sync(0xffffffffu, v, 4);
        v += __shfl_xor_sync(0xffffffffu, v, 2);
        v += __shfl_xor_sync(0xffffffffu, v, 1);
        if (lane == 0) atomicAdd(&sAcc[f], v);
    }
    __syncthreads();
    if (threadIdx.x < FC) atomicAdd(&g_hacc[threadIdx.x], sAcc[threadIdx.x]);
    __syncthreads();

    __shared__ bool isLast;
    if (threadIdx.x == 0) {
        __threadfence();
        isLast = (atomicAdd(&g_sem, 1u) == (unsigned)(gridDim.x - 1));
    }
    __syncthreads();
    if (isLast) {
        __threadfence();
        __shared__ float hv[FC];
        volatile float* vh = g_hacc;
        if (threadIdx.x < FC)
            hv[threadIdx.x] = fmaxf(vh[threadIdx.x] + fc1_b[threadIdx.x], 0.0f);
        __syncthreads();
        if (threadIdx.x < NCLS) {
            float s = fc2_b[threadIdx.x];
#pragma unroll
            for (int f = 0; f < FC; f++)
                s = fmaf(hv[f], fc2_w[threadIdx.x * FC + f], s);
            out[threadIdx.x] = s;
        }
    }
}

// ---------------------------------------------------------------------------
// launch
// ---------------------------------------------------------------------------
extern "C" void kernel_launch(void* const* d_in, const int* in_sizes, int n_in,
                              void* d_out, int out_size) {
    const float* x        = (const float*)d_in[0];
    const float* ew       = (const float*)d_in[1];
    const float* W        = (const float*)d_in[2];
    const float* bn_gamma = (const float*)d_in[3];
    const float* bn_beta  = (const float*)d_in[4];
    const float* bn_mean  = (const float*)d_in[5];
    const float* bn_var   = (const float*)d_in[6];
    const float* fc1_w    = (const float*)d_in[7];
    const float* fc1_b    = (const float*)d_in[8];
    const float* fc2_w    = (const float*)d_in[9];
    const float* fc2_b    = (const float*)d_in[10];
    const int*   ei       = (const int*)d_in[11];
    float* out            = (float*)d_out;

    proj_kernel<<<(NN * CC) / 256, 256>>>(x, bn_gamma, bn_beta, bn_mean, bn_var, W);
    hist_kernel<<<(EE + 255) / 256, 256>>>(ei);
    scanA_kernel<<<TILES, 256>>>();
    scanB_kernel<<<1, 256>>>();
    scanC_kernel<<<TILES, 256>>>();
    reorder_kernel<<<(EE + 255) / 256, 256>>>(ei, ew);
    gather_kernel<<<(NN * 32) / 256, 256>>>(W);
    gemv_head_kernel<<<GEMV_BLOCKS, GEMV_THREADS>>>(fc1_w, fc1_b, fc2_w, fc2_b, out);
}

// round 5
// speedup vs baseline: 1.2777x; 1.2460x over previous
#include <cuda_runtime.h>

// Problem constants (fixed shapes)
#define NN      50000
#define CC      32
#define HH      32
#define EE      1600000      // == NN*CC (exploited in prep)
#define NH      1600000
#define NH4     400000
#define FC      64
#define NCLS    2
#define BN_EPS  1e-5f

#define TILES   196          // ceil(NN/256)
#define CNTSZ   (TILES * 256)
#define NPB     85           // nodes per block in fused kernel
#define FGRID   589          // ceil(NN/NPB)

// Scratch (device globals; all zero at module load)
__device__ __align__(16) float g_xbn[NN * CC];
__device__ __align__(16) float g_y[NN * HH];
__device__ __align__(16) uint2 g_edges[EE];
__device__ unsigned g_cnt[CNTSZ];       // dst histogram (zeroed by fused tail)
__device__ unsigned g_rowloc[CNTSZ];    // per-tile-local exclusive offsets
__device__ unsigned g_cursor[NN];
__device__ unsigned g_bsum[256];
__device__ unsigned g_tileoff[256];
__device__ float g_hacc[FC];            // zeroed by fused tail
__device__ unsigned g_sem;              // zeroed by fused tail

// ---------------------------------------------------------------------------
// Kernel 1: BN + projection y = bn(x) @ (W1+W2) + dst histogram
// ---------------------------------------------------------------------------
__global__ __launch_bounds__(256)
void prep_kernel(const float* __restrict__ x,
                 const float* __restrict__ gamma,
                 const float* __restrict__ beta,
                 const float* __restrict__ mean,
                 const float* __restrict__ var,
                 const float* __restrict__ W,
                 const int*   __restrict__ edge_index) {
    __shared__ float sWs[CC * HH];
    for (int i = threadIdx.x; i < CC * HH; i += 256)
        sWs[i] = W[CC * HH + i] + W[2 * CC * HH + i];
    __syncthreads();

    int i = blockIdx.x * 256 + threadIdx.x;       // exactly 1.6M threads
    int lane = i & 31;

    // histogram (thread i handles edge i; EE == NN*CC)
    atomicAdd(&g_cnt[edge_index[EE + i]], 1u);

    float xv = x[i];
    float s = rsqrtf(var[lane] + BN_EPS) * gamma[lane];
    float xb = (xv - mean[lane]) * s + beta[lane];
    g_xbn[i] = xb;

    float y0 = 0.f, y1 = 0.f, y2 = 0.f, y3 = 0.f;
#pragma unroll
    for (int c = 0; c < CC; c += 4) {
        y0 = fmaf(__shfl_sync(0xffffffffu, xb, c    ), sWs[(c    ) * HH + lane], y0);
        y1 = fmaf(__shfl_sync(0xffffffffu, xb, c + 1), sWs[(c + 1) * HH + lane], y1);
        y2 = fmaf(__shfl_sync(0xffffffffu, xb, c + 2), sWs[(c + 2) * HH + lane], y2);
        y3 = fmaf(__shfl_sync(0xffffffffu, xb, c + 3), sWs[(c + 3) * HH + lane], y3);
    }
    g_y[i] = (y0 + y1) + (y2 + y3);
}

// ---------------------------------------------------------------------------
// Kernel 2: per-tile exclusive scan (local) + tile sums
// ---------------------------------------------------------------------------
__global__ void scanA_kernel() {
    __shared__ unsigned a[256], b[256];
    int idx = blockIdx.x * 256 + threadIdx.x;
    unsigned v = g_cnt[idx];
    a[threadIdx.x] = v;
    __syncthreads();
    unsigned* s = a; unsigned* d = b;
    for (int o = 1; o < 256; o <<= 1) {
        unsigned t = s[threadIdx.x];
        if (threadIdx.x >= o) t += s[threadIdx.x - o];
        d[threadIdx.x] = t;
        __syncthreads();
        unsigned* tmp = s; s = d; d = tmp;
    }
    unsigned excl = s[threadIdx.x] - v;
    g_rowloc[idx] = excl;
    if (idx < NN) g_cursor[idx] = excl;
    if (threadIdx.x == 255) g_bsum[blockIdx.x] = s[255];
}

// ---------------------------------------------------------------------------
// Kernel 3: exclusive scan of tile sums
// ---------------------------------------------------------------------------
__global__ void scanB_kernel() {
    __shared__ unsigned a[256], b[256];
    unsigned v = (threadIdx.x < TILES) ? g_bsum[threadIdx.x] : 0u;
    a[threadIdx.x] = v;
    __syncthreads();
    unsigned* s = a; unsigned* d = b;
    for (int o = 1; o < 256; o <<= 1) {
        unsigned t = s[threadIdx.x];
        if (threadIdx.x >= o) t += s[threadIdx.x - o];
        d[threadIdx.x] = t;
        __syncthreads();
        unsigned* tmp = s; s = d; d = tmp;
    }
    g_tileoff[threadIdx.x] = s[threadIdx.x] - v;
}

// ---------------------------------------------------------------------------
// Kernel 4: reorder edges into dst buckets
// ---------------------------------------------------------------------------
__global__ __launch_bounds__(256)
void reorder_kernel(const int* __restrict__ edge_index,
                    const float* __restrict__ edge_weight) {
    int e = blockIdx.x * blockDim.x + threadIdx.x;
    if (e >= EE) return;
    int s = edge_index[e];
    int d = edge_index[EE + e];
    float w = edge_weight[e];
    unsigned pos = g_tileoff[d >> 8] + atomicAdd(&g_cursor[d], 1u);
    g_edges[pos] = make_uint2((unsigned)s, __float_as_uint(w));
}

__device__ __forceinline__ unsigned row_start(int m) {
    return g_tileoff[m >> 8] + g_rowloc[m];
}

// ---------------------------------------------------------------------------
// Kernel 5: fused CSR gather + fc1 GEMV + head + next-replay cleanup
// ---------------------------------------------------------------------------
__global__ __launch_bounds__(256, 2)
void fused_kernel(const float* __restrict__ W,       // W[0] block for self-loops
                  const float* __restrict__ fc1_w,
                  const float* __restrict__ fc1_b,
                  const float* __restrict__ fc2_w,
                  const float* __restrict__ fc2_b,
                  float* __restrict__ out) {
    __shared__ float sW0[CC * HH];
    __shared__ float sres[256];
    __shared__ float sAcc[FC];
    for (int i = threadIdx.x; i < CC * HH; i += 256) sW0[i] = W[i];
    if (threadIdx.x < FC) sAcc[threadIdx.x] = 0.f;
    __syncthreads();

    // zero histogram for the NEXT replay (cnt already consumed by scanA)
    for (int idx = blockIdx.x * 256 + threadIdx.x; idx < CNTSZ; idx += FGRID * 256)
        g_cnt[idx] = 0u;

    const int tid  = threadIdx.x;
    const int w    = tid >> 5;
    const int lane = tid & 31;
    const int gfc  = tid >> 6;        // f-group 0..3
    const int i4   = tid & 63;        // float4 slot in 8-node tile
    const int nbeg = blockIdx.x * NPB;
    const int nend = min(nbeg + NPB, NN);

    float acc[16];
#pragma unroll
    for (int k = 0; k < 16; k++) acc[k] = 0.f;

    const float4* W4 = reinterpret_cast<const float4*>(fc1_w);
    const float4* R4 = reinterpret_cast<const float4*>(sres);

    for (int t0 = nbeg; t0 < nend; t0 += 8) {
        // ---------- gather phase: warp w gathers node t0+w ----------
        int n = t0 + w;
        float r = 0.f;
        if (n < nend) {
            unsigned beg = row_start(n);
            unsigned end = row_start(n + 1);
            for (unsigned j = beg; j < end; j += 32) {
                bool inr = (j + (unsigned)lane < end);
                uint2 ed = inr ? g_edges[j + lane] : make_uint2(0u, 0u);
                float wgt = inr ? __uint_as_float(ed.y) : 0.f;

                // rare self-loop(s): k=0 identity term, weight 1 each
                unsigned slm = __ballot_sync(0xffffffffu, inr && ed.x == (unsigned)n);
                if (slm) {
                    float cnt = (float)__popc(slm);
                    float xc = g_xbn[(size_t)n * CC + lane];
                    float s0 = 0.f;
#pragma unroll
                    for (int c = 0; c < CC; c++)
                        s0 = fmaf(__shfl_sync(0xffffffffu, xc, c), sW0[c * HH + lane], s0);
                    r = fmaf(cnt, s0, r);
                }
#pragma unroll
                for (int i = 0; i < 32; i++) {
                    float ww = __shfl_sync(0xffffffffu, wgt, i);
                    unsigned src = __shfl_sync(0xffffffffu, ed.x, i);
                    if (ww != 0.f)
                        r = fmaf(ww, g_y[(size_t)src * HH + lane], r);
                }
            }
        }
        sres[w * 32 + lane] = fmaxf(r, 0.f);
        __syncthreads();

        // ---------- gemv phase over this tile ----------
        int nv4 = (min(t0 + 8, nend) - t0) * 8;   // valid float4 count
        if (i4 < nv4) {
            float4 rv = R4[i4];
            size_t base = (size_t)t0 * 8 + i4;
#pragma unroll
            for (int k = 0; k < 16; k++) {
                int f = gfc * 16 + k;
                float4 wv = __ldcs(W4 + (size_t)f * NH4 + base);
                acc[k] = fmaf(rv.x, wv.x, acc[k]);
                acc[k] = fmaf(rv.y, wv.y, acc[k]);
                acc[k] = fmaf(rv.z, wv.z, acc[k]);
                acc[k] = fmaf(rv.w, wv.w, acc[k]);
            }
        }
        __syncthreads();
    }

    // ---------- block reduction ----------
#pragma unroll
    for (int k = 0; k < 16; k++) {
        float v = acc[k];
        v += __shfl_xor_sync(0xffffffffu, v, 16);
        v += __shfl_xor_sync(0xffffffffu, v, 8);
        v += __shfl_xor_sync(0xffffffffu, v, 4);
        v += __shfl_xor_sync(0xffffffffu, v, 2);
        v += __shfl_xor_sync(0xffffffffu, v, 1);
        if (lane == 0) atomicAdd(&sAcc[gfc * 16 + k], v);
    }
    __syncthreads();
    if (tid < FC) atomicAdd(&g_hacc[tid], sAcc[tid]);
    __syncthreads();

    // ---------- last block: head + cleanup ----------
    __shared__ bool isLast;
    if (tid == 0) {
        __threadfence();
        isLast = (atomicAdd(&g_sem, 1u) == (unsigned)(FGRID - 1));
    }
    __syncthreads();
    if (isLast) {
        __threadfence();
        __shared__ float hv[FC];
        volatile float* vh = g_hacc;
        if (tid < FC) hv[tid] = fmaxf(vh[tid] + fc1_b[tid], 0.f);
        __syncthreads();
        if (tid < NCLS) {
            float s = fc2_b[tid];
#pragma unroll
            for (int f = 0; f < FC; f++)
                s = fmaf(hv[f], fc2_w[tid * FC + f], s);
            out[tid] = s;
        }
        __syncthreads();
        // reset accumulators for the next replay
        if (tid < FC) g_hacc[tid] = 0.f;
        if (tid == 0) g_sem = 0u;
    }
}

// ---------------------------------------------------------------------------
// launch
// ---------------------------------------------------------------------------
extern "C" void kernel_launch(void* const* d_in, const int* in_sizes, int n_in,
                              void* d_out, int out_size) {
    const float* x        = (const float*)d_in[0];
    const float* ew       = (const float*)d_in[1];
    const float* W        = (const float*)d_in[2];
    const float* bn_gamma = (const float*)d_in[3];
    const float* bn_beta  = (const float*)d_in[4];
    const float* bn_mean  = (const float*)d_in[5];
    const float* bn_var   = (const float*)d_in[6];
    const float* fc1_w    = (const float*)d_in[7];
    const float* fc1_b    = (const float*)d_in[8];
    const float* fc2_w    = (const float*)d_in[9];
    const float* fc2_b    = (const float*)d_in[10];
    const int*   ei       = (const int*)d_in[11];
    float* out            = (float*)d_out;

    prep_kernel<<<(NN * CC) / 256, 256>>>(x, bn_gamma, bn_beta, bn_mean, bn_var, W, ei);
    scanA_kernel<<<TILES, 256>>>();
    scanB_kernel<<<1, 256>>>();
    reorder_kernel<<<(EE + 255) / 256, 256>>>(ei, ew);
    fused_kernel<<<FGRID, 256>>>(W, fc1_w, fc1_b, fc2_w, fc2_b, out);
}

// round 6
// speedup vs baseline: 1.4787x; 1.1573x over previous
#include <cuda_runtime.h>

// Problem constants (fixed shapes)
#define NN      50000
#define CC      32
#define HH      32
#define EE      1600000      // == NN*CC (exploited in prep)
#define NH      1600000
#define NH4     400000
#define FC      64
#define NCLS    2
#define BN_EPS  1e-5f

#define TILES   196          // ceil(NN/256)
#define CNTSZ   (TILES * 256)
#define NPB     88           // nodes per block (multiple of 8)
#define FGRID   569          // ceil(NN/NPB)

// Scratch (device globals; all zero at module load)
__device__ __align__(16) float g_xbn[NN * CC];
__device__ __align__(16) float g_y[NN * HH];
__device__ __align__(16) uint2 g_edges[EE];
__device__ unsigned g_cnt[CNTSZ];       // dst histogram (zeroed by fused tail)
__device__ unsigned g_rowloc[CNTSZ];    // per-tile-local exclusive offsets
__device__ unsigned g_cursor[NN];
__device__ unsigned g_bsum[256];
__device__ unsigned g_tileoff[256];
__device__ float g_hacc[FC];            // zeroed by fused tail
__device__ unsigned g_sem;              // zeroed by fused tail
__device__ unsigned g_scansem;          // zeroed by scan tail

// ---------------------------------------------------------------------------
// Kernel 1: BN + projection y = bn(x) @ (W1+W2) + dst histogram
// ---------------------------------------------------------------------------
__global__ __launch_bounds__(256)
void prep_kernel(const float* __restrict__ x,
                 const float* __restrict__ gamma,
                 const float* __restrict__ beta,
                 const float* __restrict__ mean,
                 const float* __restrict__ var,
                 const float* __restrict__ W,
                 const int*   __restrict__ edge_index) {
    __shared__ float sWs[CC * HH];
    for (int i = threadIdx.x; i < CC * HH; i += 256)
        sWs[i] = W[CC * HH + i] + W[2 * CC * HH + i];
    __syncthreads();

    int i = blockIdx.x * 256 + threadIdx.x;       // exactly 1.6M threads
    int lane = i & 31;

    // histogram (thread i handles edge i; EE == NN*CC)
    atomicAdd(&g_cnt[edge_index[EE + i]], 1u);

    float xv = x[i];
    float s = rsqrtf(var[lane] + BN_EPS) * gamma[lane];
    float xb = (xv - mean[lane]) * s + beta[lane];
    g_xbn[i] = xb;

    float y0 = 0.f, y1 = 0.f, y2 = 0.f, y3 = 0.f;
#pragma unroll
    for (int c = 0; c < CC; c += 4) {
        y0 = fmaf(__shfl_sync(0xffffffffu, xb, c    ), sWs[(c    ) * HH + lane], y0);
        y1 = fmaf(__shfl_sync(0xffffffffu, xb, c + 1), sWs[(c + 1) * HH + lane], y1);
        y2 = fmaf(__shfl_sync(0xffffffffu, xb, c + 2), sWs[(c + 2) * HH + lane], y2);
        y3 = fmaf(__shfl_sync(0xffffffffu, xb, c + 3), sWs[(c + 3) * HH + lane], y3);
    }
    g_y[i] = (y0 + y1) + (y2 + y3);
}

// ---------------------------------------------------------------------------
// Kernel 2: fused scan — per-tile exclusive scan, then last block scans tiles
// ---------------------------------------------------------------------------
__global__ void scan_kernel() {
    __shared__ unsigned a[256], b[256];
    int idx = blockIdx.x * 256 + threadIdx.x;
    unsigned v = g_cnt[idx];
    a[threadIdx.x] = v;
    __syncthreads();
    unsigned* s = a; unsigned* d = b;
    for (int o = 1; o < 256; o <<= 1) {
        unsigned t = s[threadIdx.x];
        if (threadIdx.x >= o) t += s[threadIdx.x - o];
        d[threadIdx.x] = t;
        __syncthreads();
        unsigned* tmp = s; s = d; d = tmp;
    }
    unsigned excl = s[threadIdx.x] - v;
    g_rowloc[idx] = excl;
    if (idx < NN) g_cursor[idx] = excl;
    if (threadIdx.x == 255) g_bsum[blockIdx.x] = s[255];

    // last block also scans the tile sums
    __shared__ bool isLast;
    __syncthreads();
    if (threadIdx.x == 0) {
        __threadfence();
        isLast = (atomicAdd(&g_scansem, 1u) == (unsigned)(TILES - 1));
    }
    __syncthreads();
    if (isLast) {
        __threadfence();
        unsigned w = (threadIdx.x < TILES) ? g_bsum[threadIdx.x] : 0u;
        a[threadIdx.x] = w;
        __syncthreads();
        s = a; d = b;
        for (int o = 1; o < 256; o <<= 1) {
            unsigned t = s[threadIdx.x];
            if (threadIdx.x >= o) t += s[threadIdx.x - o];
            d[threadIdx.x] = t;
            __syncthreads();
            unsigned* tmp = s; s = d; d = tmp;
        }
        g_tileoff[threadIdx.x] = s[threadIdx.x] - w;
        if (threadIdx.x == 0) g_scansem = 0u;
    }
}

// ---------------------------------------------------------------------------
// Kernel 3: reorder edges into dst buckets (2 edges per thread for ILP)
// ---------------------------------------------------------------------------
#define HALF_E (EE / 2)
__global__ __launch_bounds__(256)
void reorder_kernel(const int* __restrict__ edge_index,
                    const float* __restrict__ edge_weight) {
    int e = blockIdx.x * blockDim.x + threadIdx.x;
    if (e >= HALF_E) return;
    int e2 = e + HALF_E;

    int s1 = edge_index[e];
    int d1 = edge_index[EE + e];
    float w1 = edge_weight[e];
    int s2 = edge_index[e2];
    int d2 = edge_index[EE + e2];
    float w2 = edge_weight[e2];

    unsigned p1 = g_tileoff[d1 >> 8] + atomicAdd(&g_cursor[d1], 1u);
    unsigned p2 = g_tileoff[d2 >> 8] + atomicAdd(&g_cursor[d2], 1u);
    g_edges[p1] = make_uint2((unsigned)s1, __float_as_uint(w1));
    g_edges[p2] = make_uint2((unsigned)s2, __float_as_uint(w2));
}

__device__ __forceinline__ unsigned row_start(int m) {
    return g_tileoff[m >> 8] + g_rowloc[m];
}

// ---------------------------------------------------------------------------
// Kernel 4: fused pipelined CSR gather + fc1 GEMV + head + cleanup
// ---------------------------------------------------------------------------
__device__ __forceinline__ float gather_node(int n, int nmax, const float* sW0) {
    const int lane = threadIdx.x & 31;
    float ra = 0.f, rb = 0.f;
    if (n < nmax) {
        unsigned beg = row_start(n);
        unsigned end = row_start(n + 1);
        for (unsigned j = beg; j < end; j += 32) {
            bool inr = (j + (unsigned)lane < end);
            uint2 ed = inr ? g_edges[j + lane] : make_uint2(0u, 0u);
            float wgt = inr ? __uint_as_float(ed.y) : 0.f;

            unsigned slm = __ballot_sync(0xffffffffu, inr && ed.x == (unsigned)n);
            if (slm) {    // rare self-loop(s): k=0 identity term, weight 1 each
                float cnt = (float)__popc(slm);
                float xc = g_xbn[(size_t)n * CC + lane];
                float s0 = 0.f;
#pragma unroll
                for (int c = 0; c < CC; c++)
                    s0 = fmaf(__shfl_sync(0xffffffffu, xc, c), sW0[c * HH + lane], s0);
                ra = fmaf(cnt, s0, ra);
            }
#pragma unroll
            for (int i = 0; i < 32; i += 2) {
                float wa = __shfl_sync(0xffffffffu, wgt, i);
                unsigned sa = __shfl_sync(0xffffffffu, ed.x, i);
                float wb = __shfl_sync(0xffffffffu, wgt, i + 1);
                unsigned sb = __shfl_sync(0xffffffffu, ed.x, i + 1);
                ra = fmaf(wa, g_y[(size_t)sa * HH + lane], ra);
                rb = fmaf(wb, g_y[(size_t)sb * HH + lane], rb);
            }
        }
    }
    return fmaxf(ra + rb, 0.f);
}

__global__ __launch_bounds__(256, 2)
void fused_kernel(const float* __restrict__ W,       // W[0] block for self-loops
                  const float* __restrict__ fc1_w,
                  const float* __restrict__ fc1_b,
                  const float* __restrict__ fc2_w,
                  const float* __restrict__ fc2_b,
                  float* __restrict__ out) {
    __shared__ float sW0[CC * HH];
    __shared__ float sres[2][256];
    __shared__ float sAcc[FC];
    for (int i = threadIdx.x; i < CC * HH; i += 256) sW0[i] = W[i];
    if (threadIdx.x < FC) sAcc[threadIdx.x] = 0.f;

    // zero histogram for the NEXT replay (cnt already consumed by scan)
    for (int idx = blockIdx.x * 256 + threadIdx.x; idx < CNTSZ; idx += FGRID * 256)
        g_cnt[idx] = 0u;
    __syncthreads();

    const int tid  = threadIdx.x;
    const int w    = tid >> 5;
    const int lane = tid & 31;
    const int gfc  = tid >> 6;        // f-group 0..3
    const int i4   = tid & 63;        // float4 slot within an 8-node tile
    const int nbeg = blockIdx.x * NPB;
    const int nend = min(nbeg + NPB, NN);
    const int nt   = (nend - nbeg + 7) >> 3;   // tiles in this block

    float acc[16];
#pragma unroll
    for (int k = 0; k < 16; k++) acc[k] = 0.f;

    const float4* W4 = reinterpret_cast<const float4*>(fc1_w);

    // prologue: gather tile 0
    sres[0][w * 32 + lane] = gather_node(nbeg + w, nend, sW0);
    __syncthreads();

    for (int t = 0; t < nt; t++) {
        int cur = t & 1;
        // issue gather for tile t+1 FIRST (its L2 latency hides under gemv DRAM)
        float rnext = 0.f;
        if (t + 1 < nt)
            rnext = gather_node(nbeg + (t + 1) * 8 + w, nend, sW0);

        // gemv over tile t
        int t0 = nbeg + t * 8;
        int nv4 = (min(t0 + 8, nend) - t0) * 8;
        if (i4 < nv4) {
            float4 rv = reinterpret_cast<const float4*>(sres[cur])[i4];
            size_t base = (size_t)t0 * 8 + i4;
#pragma unroll
            for (int k = 0; k < 16; k++) {
                int f = gfc * 16 + k;
                float4 wv = __ldcs(W4 + (size_t)f * NH4 + base);
                acc[k] = fmaf(rv.x, wv.x, acc[k]);
                acc[k] = fmaf(rv.y, wv.y, acc[k]);
                acc[k] = fmaf(rv.z, wv.z, acc[k]);
                acc[k] = fmaf(rv.w, wv.w, acc[k]);
            }
        }
        sres[1 - cur][w * 32 + lane] = rnext;
        __syncthreads();
    }

    // block reduction
#pragma unroll
    for (int k = 0; k < 16; k++) {
        float v = acc[k];
        v += __shfl_xor_sync(0xffffffffu, v, 16);
        v += __shfl_xor_sync(0xffffffffu, v, 8);
        v += __shfl_xor_sync(0xffffffffu, v, 4);
        v += __shfl_xor_sync(0xffffffffu, v, 2);
        v += __shfl_xor_sync(0xffffffffu, v, 1);
        if (lane == 0) atomicAdd(&sAcc[gfc * 16 + k], v);
    }
    __syncthreads();
    if (tid < FC) atomicAdd(&g_hacc[tid], sAcc[tid]);
    __syncthreads();

    // last block: head + cleanup
    __shared__ bool isLast;
    if (tid == 0) {
        __threadfence();
        isLast = (atomicAdd(&g_sem, 1u) == (unsigned)(FGRID - 1));
    }
    __syncthreads();
    if (isLast) {
        __threadfence();
        __shared__ float hv[FC];
        volatile float* vh = g_hacc;
        if (tid < FC) hv[tid] = fmaxf(vh[tid] + fc1_b[tid], 0.f);
        __syncthreads();
        if (tid < NCLS) {
            float s = fc2_b[tid];
#pragma unroll
            for (int f = 0; f < FC; f++)
                s = fmaf(hv[f], fc2_w[tid * FC + f], s);
            out[tid] = s;
        }
        __syncthreads();
        if (tid < FC) g_hacc[tid] = 0.f;
        if (tid == 0) g_sem = 0u;
    }
}

// ---------------------------------------------------------------------------
// launch
// ---------------------------------------------------------------------------
extern "C" void kernel_launch(void* const* d_in, const int* in_sizes, int n_in,
                              void* d_out, int out_size) {
    const float* x        = (const float*)d_in[0];
    const float* ew       = (const float*)d_in[1];
    const float* W        = (const float*)d_in[2];
    const float* bn_gamma = (const float*)d_in[3];
    const float* bn_beta  = (const float*)d_in[4];
    const float* bn_mean  = (const float*)d_in[5];
    const float* bn_var   = (const float*)d_in[6];
    const float* fc1_w    = (const float*)d_in[7];
    const float* fc1_b    = (const float*)d_in[8];
    const float* fc2_w    = (const float*)d_in[9];
    const float* fc2_b    = (const float*)d_in[10];
    const int*   ei       = (const int*)d_in[11];
    float* out            = (float*)d_out;

    prep_kernel<<<(NN * CC) / 256, 256>>>(x, bn_gamma, bn_beta, bn_mean, bn_var, W, ei);
    scan_kernel<<<TILES, 256>>>();
    reorder_kernel<<<(HALF_E + 255) / 256, 256>>>(ei, ew);
    fused_kernel<<<FGRID, 256>>>(W, fc1_w, fc1_b, fc2_w, fc2_b, out);
}